// round 1
// baseline (speedup 1.0000x reference)
#include <cuda_runtime.h>
#include <math.h>
#include <stdint.h>

// Problem constants
#define B 16
#define S 2048
#define M 4
#define E 128
#define HH 128
#define VOCAB 100000
#define NE 4000
#define NR 200

// ---------------- device scratch (no allocation allowed) ----------------
__device__ float g_h[B * HH];
__device__ float g_u[B * HH];
__device__ float g_logit[B * S];
__device__ float g_prob[B * S];
__device__ float g_partial[B * 32 * HH];
__device__ float g_noisy[B * NE];   // reused per head (max N = 4000)

// ---------------- threefry2x32-20 (JAX) ----------------
__host__ __device__ __forceinline__ uint32_t rotl32(uint32_t v, int d) {
    return (v << d) | (v >> (32 - d));
}

__host__ __device__ __forceinline__ void threefry2x32(
    uint32_t k0, uint32_t k1, uint32_t x0, uint32_t x1,
    uint32_t& o0, uint32_t& o1)
{
    uint32_t ks0 = k0, ks1 = k1;
    uint32_t ks2 = k0 ^ k1 ^ 0x1BD11BDAu;
    x0 += ks0; x1 += ks1;
    const int rA[4] = {13, 15, 26, 6};
    const int rB[4] = {17, 29, 16, 24};
    #pragma unroll
    for (int i = 0; i < 4; i++) { x0 += x1; x1 = rotl32(x1, rA[i]); x1 ^= x0; }
    x0 += ks1; x1 += ks2 + 1u;
    #pragma unroll
    for (int i = 0; i < 4; i++) { x0 += x1; x1 = rotl32(x1, rB[i]); x1 ^= x0; }
    x0 += ks2; x1 += ks0 + 2u;
    #pragma unroll
    for (int i = 0; i < 4; i++) { x0 += x1; x1 = rotl32(x1, rA[i]); x1 ^= x0; }
    x0 += ks0; x1 += ks1 + 3u;
    #pragma unroll
    for (int i = 0; i < 4; i++) { x0 += x1; x1 = rotl32(x1, rB[i]); x1 ^= x0; }
    x0 += ks1; x1 += ks2 + 4u;
    #pragma unroll
    for (int i = 0; i < 4; i++) { x0 += x1; x1 = rotl32(x1, rA[i]); x1 ^= x0; }
    x0 += ks2; x1 += ks0 + 5u;
    o0 = x0; o1 = x1;
}

#define FULLMASK 0xffffffffu

// ---------------- h = hidden @ Wm^T + Wb ; u = h ----------------
__global__ void k_h(const float* __restrict__ hidden,
                    const float* __restrict__ Wm,
                    const float* __restrict__ Wb)
{
    int b = blockIdx.x, t = threadIdx.x;
    __shared__ float sh[HH];
    sh[t] = hidden[b * HH + t];
    __syncthreads();
    float acc = Wb[t];
    const float* w = Wm + (size_t)t * HH;
    #pragma unroll 8
    for (int k = 0; k < HH; k++) acc = fmaf(w[k], sh[k], acc);
    g_h[b * HH + t] = acc;
    g_u[b * HH + t] = acc;
}

// ---------------- head: logits + gumbel-noised logits ----------------
// out_logit = h @ W^T + bias (written to d_out); g_noisy = logit + gumbel
__global__ void k_head(const float* __restrict__ W,
                       const float* __restrict__ bias,
                       int N, uint32_t ka, uint32_t kb,
                       float* __restrict__ out_logit)
{
    int gid  = blockIdx.x * blockDim.x + threadIdx.x;
    int warp = gid >> 5, lane = gid & 31;
    if (warp >= B * N) return;
    int b = warp / N, n = warp - b * N;
    float4 w4 = __ldg((const float4*)(W + (size_t)n * HH) + lane);
    float4 h4 = *((const float4*)(g_h + b * HH) + lane);
    float s = w4.x * h4.x + w4.y * h4.y + w4.z * h4.z + w4.w * h4.w;
    #pragma unroll
    for (int o = 16; o; o >>= 1) s += __shfl_down_sync(FULLMASK, s, o);
    if (lane == 0) {
        int i = b * N + n;
        float logit = s + __ldg(bias + n);
        out_logit[i] = logit;
        // JAX partitionable random_bits: bits[i] = lane0 ^ lane1 of tf(key,(0,i))
        uint32_t o0, o1;
        threefry2x32(ka, kb, 0u, (uint32_t)i, o0, o1);
        uint32_t bits = o0 ^ o1;
        float u = __uint_as_float((bits >> 9) | 0x3F800000u) - 1.0f;
        float v = fmaxf(1e-10f, u + 1e-10f);     // (maxval-minval)==1.0f in f32
        float g = -logf(-logf(v));
        g_noisy[i] = logit + g;
    }
}

// ---------------- argmax of noisy logits -> one-hot ----------------
__global__ void k_argmax_onehot(int N, float* __restrict__ out_action)
{
    int b = blockIdx.x, t = threadIdx.x;
    const float* row = g_noisy + b * N;
    float bv = -INFINITY; int bi = 0x7fffffff;
    for (int i = t; i < N; i += blockDim.x) {
        float v = row[i];
        if (v > bv || (v == bv && i < bi)) { bv = v; bi = i; }
    }
    __shared__ float sv[256];
    __shared__ int   si[256];
    sv[t] = bv; si[t] = bi;
    __syncthreads();
    for (int o = 128; o; o >>= 1) {
        if (t < o) {
            if (sv[t + o] > sv[t] || (sv[t + o] == sv[t] && si[t + o] < si[t])) {
                sv[t] = sv[t + o]; si[t] = si[t + o];
            }
        }
        __syncthreads();
    }
    int best = si[0];
    float* out = out_action + b * N;
    for (int i = t; i < N; i += blockDim.x) out[i] = (i == best) ? 1.0f : 0.0f;
}

// ---------------- hop logit: logit[b,s] = (sum_m C[story[b,s,m]]) . u[b] ----------------
__global__ void k_hop_logit(const int* __restrict__ story,
                            const float* __restrict__ Ct)
{
    int gid  = blockIdx.x * blockDim.x + threadIdx.x;
    int warp = gid >> 5, lane = gid & 31;
    if (warp >= B * S) return;
    int b = warp >> 11;
    int4 idx = __ldg((const int4*)story + warp);
    float4 a = __ldg((const float4*)(Ct + (size_t)idx.x * E) + lane);
    float4 c = __ldg((const float4*)(Ct + (size_t)idx.y * E) + lane);
    float4 d = __ldg((const float4*)(Ct + (size_t)idx.z * E) + lane);
    float4 e = __ldg((const float4*)(Ct + (size_t)idx.w * E) + lane);
    float4 u4 = *((const float4*)(g_u + b * HH) + lane);
    float s = (a.x + c.x + d.x + e.x) * u4.x
            + (a.y + c.y + d.y + e.y) * u4.y
            + (a.z + c.z + d.z + e.z) * u4.z
            + (a.w + c.w + d.w + e.w) * u4.w;
    #pragma unroll
    for (int o = 16; o; o >>= 1) s += __shfl_down_sync(FULLMASK, s, o);
    if (lane == 0) g_logit[warp] = s;
}

// ---------------- softmax over S per batch ----------------
__global__ void k_softmax()
{
    int b = blockIdx.x, t = threadIdx.x; // 256 threads
    const float* l = g_logit + b * S;
    float* p = g_prob + b * S;
    __shared__ float red[256];
    float m = -INFINITY;
    for (int i = t; i < S; i += 256) m = fmaxf(m, l[i]);
    red[t] = m; __syncthreads();
    for (int o = 128; o; o >>= 1) { if (t < o) red[t] = fmaxf(red[t], red[t + o]); __syncthreads(); }
    m = red[0]; __syncthreads();
    float sum = 0.f;
    for (int i = t; i < S; i += 256) { float e = expf(l[i] - m); p[i] = e; sum += e; }
    red[t] = sum; __syncthreads();
    for (int o = 128; o; o >>= 1) { if (t < o) red[t] += red[t + o]; __syncthreads(); }
    float inv = 1.0f / red[0];
    for (int i = t; i < S; i += 256) p[i] *= inv;
}

// ---------------- u update partials: acc_e = sum_s prob[b,s] * sum_m C[story] ----------------
__global__ void k_update_partial(const int* __restrict__ story,
                                 const float* __restrict__ Ct)
{
    int b = blockIdx.y, chunk = blockIdx.x;
    int e = threadIdx.x; // 128
    float acc = 0.f;
    int s0 = chunk * (S / 32);
    for (int s = s0; s < s0 + (S / 32); s++) {
        float p = g_prob[b * S + s];
        int4 idx = __ldg((const int4*)story + b * S + s);
        float v = __ldg(Ct + (size_t)idx.x * E + e)
                + __ldg(Ct + (size_t)idx.y * E + e)
                + __ldg(Ct + (size_t)idx.z * E + e)
                + __ldg(Ct + (size_t)idx.w * E + e);
        acc = fmaf(p, v, acc);
    }
    g_partial[(b * 32 + chunk) * HH + e] = acc;
}

__global__ void k_update_reduce()
{
    int b = blockIdx.x, e = threadIdx.x;
    float acc = 0.f;
    #pragma unroll
    for (int c = 0; c < 32; c++) acc += g_partial[(b * 32 + c) * HH + e];
    g_u[b * HH + e] += acc;
}

// ---------------- masked sigmoid of final logits ----------------
__global__ void k_mask(const int* __restrict__ lengths, float* __restrict__ out)
{
    int i = blockIdx.x * blockDim.x + threadIdx.x;
    if (i >= B * S) return;
    int b = i >> 11, s = i & (S - 1);
    float v = 0.f;
    if (s < __ldg(lengths + b)) {
        float l = g_logit[i];
        v = 1.0f / (1.0f + expf(-l));
    }
    out[i] = v;
}

// ---------------- host launch ----------------
extern "C" void kernel_launch(void* const* d_in, const int* in_sizes, int n_in,
                              void* d_out, int out_size)
{
    const int*   story   = (const int*)d_in[0];
    const int*   lengths = (const int*)d_in[1];
    const float* hidden  = (const float*)d_in[2];
    // d_in[3] global_pointer: unused (is_decoding == 0 path)
    const float* C       = (const float*)d_in[4];
    const float* Wm      = (const float*)d_in[5];
    const float* Wb      = (const float*)d_in[6];
    const float* W1w     = (const float*)d_in[7];
    const float* W1b     = (const float*)d_in[8];
    const float* W3w     = (const float*)d_in[9];
    const float* W3b     = (const float*)d_in[10];
    const float* W4w     = (const float*)d_in[11];
    const float* W4b     = (const float*)d_in[12];
    // d_in[13] is_decoding: unused

    float* out = (float*)d_out;
    float* o_sp   = out;                       // [B,2]
    float* o_spa  = out + B * 2;               // [B,2]
    float* o_qh   = out + B * 4;               // [B,4000]
    float* o_qha  = o_qh + B * NE;             // [B,4000]
    float* o_qt   = o_qha + B * NE;            // [B,200]
    float* o_qta  = o_qt + B * NR;             // [B,200]
    float* o_mask = o_qta + B * NR;            // [B,S]

    // JAX partitionable split of key(42): k_i = threefry(key, (0, i))
    uint32_t k1a, k1b, k2a, k2b, k3a, k3b;
    threefry2x32(0u, 42u, 0u, 0u, k1a, k1b);
    threefry2x32(0u, 42u, 0u, 1u, k2a, k2b);
    threefry2x32(0u, 42u, 0u, 2u, k3a, k3b);

    k_h<<<B, HH>>>(hidden, Wm, Wb);

    // heads: sp (N=2, key1), qh (N=4000, key2), qt (N=200, key3)
    {
        int N = 2;
        int blocks = (B * N * 32 + 255) / 256;
        k_head<<<blocks, 256>>>(W1w, W1b, N, k1a, k1b, o_sp);
        k_argmax_onehot<<<B, 256>>>(N, o_spa);
    }
    {
        int N = NE;
        int blocks = (B * N * 32 + 255) / 256;
        k_head<<<blocks, 256>>>(W3w, W3b, N, k2a, k2b, o_qh);
        k_argmax_onehot<<<B, 256>>>(N, o_qha);
    }
    {
        int N = NR;
        int blocks = (B * N * 32 + 255) / 256;
        k_head<<<blocks, 256>>>(W4w, W4b, N, k3a, k3b, o_qt);
        k_argmax_onehot<<<B, 256>>>(N, o_qta);
    }

    // memory hops: full pass for hop 0,1; hop 2 only needs the logits
    const size_t TBL = (size_t)VOCAB * E;
    for (int hop = 0; hop < 2; hop++) {
        k_hop_logit<<<(B * S * 32) / 256, 256>>>(story, C + (size_t)hop * TBL);
        k_softmax<<<B, 256>>>();
        dim3 g(32, B);
        k_update_partial<<<g, 128>>>(story, C + (size_t)(hop + 1) * TBL);
        k_update_reduce<<<B, HH>>>();
    }
    k_hop_logit<<<(B * S * 32) / 256, 256>>>(story, C + (size_t)2 * TBL);

    k_mask<<<(B * S + 255) / 256, 256>>>(lengths, o_mask);
}